// round 2
// baseline (speedup 1.0000x reference)
#include <cuda_runtime.h>
#include <cstdint>

// Problem constants (fixed by setup_inputs: n_bins=2)
#define CCH 8
#define NBF 2.0f
#define DS  21
#define SLOTS 40                     // per (n,c): [x=5][ycell=4][ly=2] complex slots
#define NHIST_F4 8000000             // 50000*8*40 float2 = 16M float2 = 8M float4 = 128 MB

// Grid-coordinate histogram accumulator, 16B aligned for v4 REDs.
__device__ float4 g_hist[NHIST_F4];

__global__ void zero_kernel(int n4) {
    int i = blockIdx.x * blockDim.x + threadIdx.x;
    if (i < n4) g_hist[i] = make_float4(0.f, 0.f, 0.f, 0.f);
}

__global__ __launch_bounds__(256) void scatter_kernel(
    const float2* __restrict__ x,       // [N*C] complex
    const int2*   __restrict__ edges,   // [E] (src, tgt)
    const float2* __restrict__ ln,      // [E] complex
    const float2* __restrict__ wxp,     // [E] complex
    int total)                          // E * C
{
    int tid = blockIdx.x * blockDim.x + threadIdx.x;
    if (tid >= total) return;
    int e = tid >> 3;
    int c = tid & 7;

    int2 ed = edges[e];
    float2 xs = x[ed.x * CCH + c];

    float norm = xs.x * xs.x + xs.y * xs.y;
    if (norm == 0.0f) return;  // nz mask: all contributions exactly 0 in reference

    float2 l = ln[e];
    float2 w = wxp[e];

    // p = ln * conj(x_src)/|x_src| * n_bins
    float s  = NBF * rsqrtf(norm);
    float pr = (l.x * xs.x + l.y * xs.y) * s;
    float pi = (l.y * xs.x - l.x * xs.y) * s;

    float pCx = fminf(fmaxf(ceilf(pr),  -NBF), NBF);
    float pCy = fminf(fmaxf(ceilf(pi),  -NBF), NBF);
    float pFx = fminf(fmaxf(floorf(pr), -NBF), NBF);
    float pFy = fminf(fmaxf(floorf(pi), -NBF), NBF);

    float r0 = (pCx - pr) * (pCy - pi);   // grid (Fx,Fy)
    float r1 = (pr - pFx) * (pi - pFy);   // grid (Cx,Cy)
    float r2 = (pr - pFx) * (pCy - pi);   // grid (Cx,Fy)
    float r3 = (pCx - pr) * (pi - pFy);   // grid (Fx,Cy)

    int fxI = (int)pFx + 2, cxI = (int)pCx + 2;
    int fyI = (int)pFy + 2, cyI = (int)pCy + 2;

    int ycell = fyI < 3 ? fyI : 3;        // y-cell covering slots ly=0 (y=ycell) and ly=1 (y=ycell+1)
    int lyF = fyI - ycell;                // 0 or 1
    int lyC = cyI - ycell;                // 0 or 1

    // Fold the two y-corner weights into the 2-slot pair (degenerate corners sum).
    float sF0 = (lyF == 0 ? r0 : 0.f) + (lyC == 0 ? r3 : 0.f);
    float sF1 = (lyF != 0 ? r0 : 0.f) + (lyC != 0 ? r3 : 0.f);
    float sC0 = (lyF == 0 ? r2 : 0.f) + (lyC == 0 ? r1 : 0.f);
    float sC1 = (lyF != 0 ? r2 : 0.f) + (lyC != 0 ? r1 : 0.f);

    // xW = x_src * wxp
    float wr = xs.x * w.x - xs.y * w.y;
    float wi = xs.x * w.y + xs.y * w.x;

    float2* base = reinterpret_cast<float2*>(g_hist) + (long)(ed.y * CCH + c) * SLOTS;
    float2* rowF = base + fxI * 8 + ycell * 2;   // even float2 index -> 16B aligned
    float2* rowC = base + cxI * 8 + ycell * 2;

    asm volatile("red.global.add.v4.f32 [%0], {%1, %2, %3, %4};"
                 :: "l"(rowF), "f"(wr * sF0), "f"(wi * sF0), "f"(wr * sF1), "f"(wi * sF1)
                 : "memory");
    asm volatile("red.global.add.v4.f32 [%0], {%1, %2, %3, %4};"
                 :: "l"(rowC), "f"(wr * sC0), "f"(wi * sC0), "f"(wr * sC1), "f"(wi * sC1)
                 : "memory");
}

// dMap grid (row-major 5x5); excluded corners alias to bin 0 (matches reference).
__device__ __constant__ int c_dmap[25] = {
     0,  0,  1,  2,  0,
     3,  4,  5,  6,  7,
     8,  9, 10, 11, 12,
    13, 14, 15, 16, 17,
     0, 18, 19, 20,  0
};

__global__ void finalize_kernel(float* __restrict__ out, int n_nc) {
    int nc = blockIdx.x * blockDim.x + threadIdx.x;
    if (nc >= n_nc) return;

    const float4* src = g_hist + (long)nc * (SLOTS / 2);   // 20 float4 = 40 float2 slots
    float2 slot[SLOTS];
    #pragma unroll
    for (int i = 0; i < SLOTS / 2; i++) {
        float4 v = src[i];
        slot[2 * i]     = make_float2(v.x, v.y);
        slot[2 * i + 1] = make_float2(v.z, v.w);
    }

    // Reconstruct 5x5 grid: grid(x,y) = slot[x][y][0] (y<=3) + slot[x][y-1][1] (y>=1)
    float2 g[5][5];
    #pragma unroll
    for (int xr = 0; xr < 5; xr++) {
        #pragma unroll
        for (int y = 0; y < 5; y++) {
            float re = 0.f, im = 0.f;
            if (y <= 3) { re += slot[xr * 8 + y * 2].x;       im += slot[xr * 8 + y * 2].y; }
            if (y >= 1) { re += slot[xr * 8 + (y - 1) * 2 + 1].x; im += slot[xr * 8 + (y - 1) * 2 + 1].y; }
            g[xr][y] = make_float2(re, im);
        }
    }

    float bre[DS], bim[DS];
    #pragma unroll
    for (int b = 0; b < DS; b++) { bre[b] = 0.f; bim[b] = 0.f; }
    #pragma unroll
    for (int xr = 0; xr < 5; xr++) {
        #pragma unroll
        for (int y = 0; y < 5; y++) {
            int b = c_dmap[xr * 5 + y];
            bre[b] += g[xr][y].x;
            bim[b] += g[xr][y].y;
        }
    }

    float* o = out + (long)nc * DS;
    #pragma unroll
    for (int b = 0; b < DS; b++)
        o[b] = sqrtf(bre[b] * bre[b] + bim[b] * bim[b] + 1e-12f);
}

extern "C" void kernel_launch(void* const* d_in, const int* in_sizes, int n_in,
                              void* d_out, int out_size)
{
    const float2* x     = (const float2*)d_in[0];  // (N, C, 2) f32
    const int2*   edges = (const int2*)  d_in[1];  // (E, 2) i32
    const float2* ln    = (const float2*)d_in[2];  // (E, 2) f32
    const float2* wxp   = (const float2*)d_in[3];  // (E, 2) f32

    int E = in_sizes[1] / 2;
    int n_nc = out_size / DS;                      // N*C

    int n4 = n_nc * (SLOTS / 2);                   // float4 count to zero
    zero_kernel<<<(n4 + 255) / 256, 256>>>(n4);

    int total = E * CCH;
    scatter_kernel<<<(total + 255) / 256, 256>>>(x, edges, ln, wxp, total);

    finalize_kernel<<<(n_nc + 255) / 256, 256>>>((float*)d_out, n_nc);
}

// round 3
// speedup vs baseline: 1.1308x; 1.1308x over previous
#include <cuda_runtime.h>
#include <cstdint>

// Problem constants (fixed by setup_inputs: n_bins=2)
#define CCH 8
#define NBF 2.0f
#define DS  21
#define SLOTS 30                      // per (n,c): [x=5][y=6 (5 used + 1 pad)] complex
#define NHIST_F4 6000000              // 50000*8*30 float2 = 12M float2 = 6M float4 = 96 MB

// Grid-coordinate histogram accumulator; (n,c) stride 240B, rows 48B -> 16B aligned v4 targets.
__device__ float4 g_hist[NHIST_F4];

__global__ void zero_kernel(int n4) {
    int i = blockIdx.x * blockDim.x + threadIdx.x;
    if (i < n4) g_hist[i] = make_float4(0.f, 0.f, 0.f, 0.f);
}

__device__ __forceinline__ void red_v2(float2* p, float re, float im) {
    asm volatile("red.global.add.v2.f32 [%0], {%1, %2};"
                 :: "l"(p), "f"(re), "f"(im) : "memory");
}
__device__ __forceinline__ void red_v4(float2* p, float re0, float im0, float re1, float im1) {
    asm volatile("red.global.add.v4.f32 [%0], {%1, %2, %3, %4};"
                 :: "l"(p), "f"(re0), "f"(im0), "f"(re1), "f"(im1) : "memory");
}

// Emit one x-row's two y-corner contributions with minimal RED lanes.
// aF = scalar weight at y=fyI, aC = scalar weight at y=cyI (cyI == fyI or fyI+1).
__device__ __forceinline__ void emit_row(float2* row, int fyI, int cyI,
                                         float aF, float aC, float wr, float wi)
{
    if (fyI == cyI) {
        float a = aF + aC;
        red_v2(row + fyI, wr * a, wi * a);
    } else if ((fyI & 1) == 0) {
        red_v4(row + fyI, wr * aF, wi * aF, wr * aC, wi * aC);
    } else {
        red_v2(row + fyI, wr * aF, wi * aF);
        red_v2(row + cyI, wr * aC, wi * aC);
    }
}

__global__ __launch_bounds__(256) void scatter_kernel(
    const float2* __restrict__ x,       // [N*C] complex
    const int2*   __restrict__ edges,   // [E] (src, tgt)
    const float2* __restrict__ ln,      // [E] complex
    const float2* __restrict__ wxp,     // [E] complex
    int total)                          // E * C
{
    int tid = blockIdx.x * blockDim.x + threadIdx.x;
    if (tid >= total) return;
    int e = tid >> 3;
    int c = tid & 7;

    int2 ed = edges[e];
    float2 xs = x[ed.x * CCH + c];

    float norm = xs.x * xs.x + xs.y * xs.y;
    if (norm == 0.0f) return;  // nz mask: contributions exactly 0 in reference

    float2 l = ln[e];
    float2 w = wxp[e];

    // p = ln * conj(x_src)/|x_src| * n_bins   (one NR step for accuracy margin)
    float r  = rsqrtf(norm);
    r = r * (1.5f - 0.5f * norm * r * r);
    float s  = NBF * r;
    float pr = (l.x * xs.x + l.y * xs.y) * s;
    float pi = (l.y * xs.x - l.x * xs.y) * s;

    float pCx = fminf(fmaxf(ceilf(pr),  -NBF), NBF);
    float pCy = fminf(fmaxf(ceilf(pi),  -NBF), NBF);
    float pFx = fminf(fmaxf(floorf(pr), -NBF), NBF);
    float pFy = fminf(fmaxf(floorf(pi), -NBF), NBF);

    float r0 = (pCx - pr) * (pCy - pi);   // grid (Fx,Fy)
    float r1 = (pr - pFx) * (pi - pFy);   // grid (Cx,Cy)
    float r2 = (pr - pFx) * (pCy - pi);   // grid (Cx,Fy)
    float r3 = (pCx - pr) * (pi - pFy);   // grid (Fx,Cy)

    int fxI = (int)pFx + 2, cxI = (int)pCx + 2;
    int fyI = (int)pFy + 2, cyI = (int)pCy + 2;

    // xW = x_src * wxp
    float wr = xs.x * w.x - xs.y * w.y;
    float wi = xs.x * w.y + xs.y * w.x;

    float2* base = reinterpret_cast<float2*>(g_hist) + (long)(ed.y * CCH + c) * SLOTS;

    if (fxI == cxI) {
        // rows coincide: merge corner weights (r0+r2 at fy, r3+r1 at cy)
        emit_row(base + fxI * 6, fyI, cyI, r0 + r2, r3 + r1, wr, wi);
    } else {
        emit_row(base + fxI * 6, fyI, cyI, r0, r3, wr, wi);
        emit_row(base + cxI * 6, fyI, cyI, r2, r1, wr, wi);
    }
}

// dMap grid (row-major 5x5); excluded corners alias to bin 0 (matches reference).
__device__ __constant__ int c_dmap[25] = {
     0,  0,  1,  2,  0,
     3,  4,  5,  6,  7,
     8,  9, 10, 11, 12,
    13, 14, 15, 16, 17,
     0, 18, 19, 20,  0
};

__global__ void finalize_kernel(float* __restrict__ out, int n_nc) {
    int nc = blockIdx.x * blockDim.x + threadIdx.x;
    if (nc >= n_nc) return;

    const float4* src = g_hist + (long)nc * (SLOTS / 2);   // 15 float4 = 30 float2 slots
    float2 slot[SLOTS];
    #pragma unroll
    for (int i = 0; i < SLOTS / 2; i++) {
        float4 v = src[i];
        slot[2 * i]     = make_float2(v.x, v.y);
        slot[2 * i + 1] = make_float2(v.z, v.w);
    }

    float bre[DS], bim[DS];
    #pragma unroll
    for (int b = 0; b < DS; b++) { bre[b] = 0.f; bim[b] = 0.f; }
    #pragma unroll
    for (int xr = 0; xr < 5; xr++) {
        #pragma unroll
        for (int y = 0; y < 5; y++) {
            int b = c_dmap[xr * 5 + y];
            bre[b] += slot[xr * 6 + y].x;
            bim[b] += slot[xr * 6 + y].y;
        }
    }

    float* o = out + (long)nc * DS;
    #pragma unroll
    for (int b = 0; b < DS; b++)
        o[b] = sqrtf(bre[b] * bre[b] + bim[b] * bim[b] + 1e-12f);
}

extern "C" void kernel_launch(void* const* d_in, const int* in_sizes, int n_in,
                              void* d_out, int out_size)
{
    const float2* x     = (const float2*)d_in[0];  // (N, C, 2) f32
    const int2*   edges = (const int2*)  d_in[1];  // (E, 2) i32
    const float2* ln    = (const float2*)d_in[2];  // (E, 2) f32
    const float2* wxp   = (const float2*)d_in[3];  // (E, 2) f32

    int E = in_sizes[1] / 2;
    int n_nc = out_size / DS;                      // N*C

    int n4 = n_nc * (SLOTS / 2);                   // float4 count to zero
    zero_kernel<<<(n4 + 255) / 256, 256>>>(n4);

    int total = E * CCH;
    scatter_kernel<<<(total + 255) / 256, 256>>>(x, edges, ln, wxp, total);

    finalize_kernel<<<(n_nc + 255) / 256, 256>>>((float*)d_out, n_nc);
}

// round 4
// speedup vs baseline: 1.8384x; 1.6257x over previous
#include <cuda_runtime.h>
#include <cstdint>

// Problem constants (fixed by setup_inputs: n_bins=2)
#define CCH 8
#define NBF 2.0f
#define DS  21
#define DSP 22                        // padded bins per (n,c): 176B, 16B-aligned base
#define NHIST_F4 4400000              // 50000*8*22 float2 = 8.8M float2 = 4.4M float4 = 70.4 MB

__device__ float4 g_hist[NHIST_F4];

__global__ void zero_kernel(int n4) {
    int i = blockIdx.x * blockDim.x + threadIdx.x;
    if (i < n4) g_hist[i] = make_float4(0.f, 0.f, 0.f, 0.f);
}

__device__ __forceinline__ void red_v2(float2* p, float re, float im) {
    asm volatile("red.global.add.v2.f32 [%0], {%1, %2};"
                 :: "l"(p), "f"(re), "f"(im) : "memory");
}
__device__ __forceinline__ void red_v4(float2* p, float re0, float im0, float re1, float im1) {
    asm volatile("red.global.add.v4.f32 [%0], {%1, %2, %3, %4};"
                 :: "l"(p), "f"(re0), "f"(im0), "f"(re1), "f"(im1) : "memory");
}

// dMap(5x5) packed 5 bits/entry into two 64-bit words (ALU-only lookup).
// flat: [0,0,1,2,0, 3,4,5,6,7, 8,9,10,11,12, 13,14,15,16,17, 0,18,19,20,0]
__device__ __forceinline__ int dbin(int idx) {
    constexpr unsigned long long m0 =
        (0ULL<<0)|(0ULL<<5)|(1ULL<<10)|(2ULL<<15)|(0ULL<<20)|
        (3ULL<<25)|(4ULL<<30)|(5ULL<<35)|(6ULL<<40)|(7ULL<<45)|
        (8ULL<<50)|(9ULL<<55);
    constexpr unsigned long long m1 =
        (10ULL<<0)|(11ULL<<5)|(12ULL<<10)|(13ULL<<15)|(14ULL<<20)|
        (15ULL<<25)|(16ULL<<30)|(17ULL<<35)|(0ULL<<40)|(18ULL<<45)|
        (19ULL<<50)|(20ULL<<55);
    unsigned long long m = idx < 12 ? m0 : m1;
    int sh = 5 * (idx < 12 ? idx : idx - 12);
    int b = (int)((m >> sh) & 31);
    return idx >= 24 ? 0 : b;
}

// Emit one x-row's two y-corner contributions into compact bin space.
// base is the (n,c) bin array (16B-aligned). cy == fy or fy+1.
__device__ __forceinline__ void emit_row(float2* base, int xr, int fy, int cy,
                                         float aF, float aC, float wr, float wi)
{
    int bF = dbin(5 * xr + fy);
    int bC = dbin(5 * xr + cy);
    if (bF == bC) {
        float a = aF + aC;
        red_v2(base + bF, wr * a, wi * a);
    } else if (bC == bF + 1 && (bF & 1) == 0) {
        red_v4(base + bF, wr * aF, wi * aF, wr * aC, wi * aC);
    } else {
        red_v2(base + bF, wr * aF, wi * aF);
        red_v2(base + bC, wr * aC, wi * aC);
    }
}

__global__ __launch_bounds__(256) void scatter_kernel(
    const float2* __restrict__ x,       // [N*C] complex
    const int2*   __restrict__ edges,   // [E] (src, tgt)
    const float2* __restrict__ ln,      // [E] complex
    const float2* __restrict__ wxp,     // [E] complex
    int total)                          // E * C
{
    int tid = blockIdx.x * blockDim.x + threadIdx.x;
    if (tid >= total) return;
    int e = tid >> 3;
    int c = tid & 7;

    int2 ed = edges[e];
    float2 xs = x[ed.x * CCH + c];

    float norm = xs.x * xs.x + xs.y * xs.y;
    if (norm == 0.0f) return;  // nz mask: contributions exactly 0 in reference

    float2 l = ln[e];
    float2 w = wxp[e];

    // p = ln * conj(x_src)/|x_src| * n_bins
    float r  = rsqrtf(norm);
    r = r * (1.5f - 0.5f * norm * r * r);
    float s  = NBF * r;
    float pr = (l.x * xs.x + l.y * xs.y) * s;
    float pi = (l.y * xs.x - l.x * xs.y) * s;

    float pCx = fminf(fmaxf(ceilf(pr),  -NBF), NBF);
    float pCy = fminf(fmaxf(ceilf(pi),  -NBF), NBF);
    float pFx = fminf(fmaxf(floorf(pr), -NBF), NBF);
    float pFy = fminf(fmaxf(floorf(pi), -NBF), NBF);

    float r0 = (pCx - pr) * (pCy - pi);   // grid (Fx,Fy)
    float r1 = (pr - pFx) * (pi - pFy);   // grid (Cx,Cy)
    float r2 = (pr - pFx) * (pCy - pi);   // grid (Cx,Fy)
    float r3 = (pCx - pr) * (pi - pFy);   // grid (Fx,Cy)

    int fxI = (int)pFx + 2, cxI = (int)pCx + 2;
    int fyI = (int)pFy + 2, cyI = (int)pCy + 2;

    // xW = x_src * wxp
    float wr = xs.x * w.x - xs.y * w.y;
    float wi = xs.x * w.y + xs.y * w.x;

    float2* base = reinterpret_cast<float2*>(g_hist) + (long)(ed.y * CCH + c) * DSP;

    if (fxI == cxI) {
        emit_row(base, fxI, fyI, cyI, r0 + r2, r3 + r1, wr, wi);
    } else {
        emit_row(base, fxI, fyI, cyI, r0, r3, wr, wi);
        emit_row(base, cxI, fyI, cyI, r2, r1, wr, wi);
    }
}

__global__ void finalize_kernel(float* __restrict__ out, int n_nc) {
    int nc = blockIdx.x * blockDim.x + threadIdx.x;
    if (nc >= n_nc) return;

    const float4* src = g_hist + (long)nc * (DSP / 2);   // 11 float4 = 22 float2 bins
    float* o = out + (long)nc * DS;
    #pragma unroll
    for (int i = 0; i < DSP / 2; i++) {
        float4 v = src[i];
        int b = 2 * i;
        o[b] = sqrtf(v.x * v.x + v.y * v.y + 1e-12f);
        if (b + 1 < DS)
            o[b + 1] = sqrtf(v.z * v.z + v.w * v.w + 1e-12f);
    }
}

extern "C" void kernel_launch(void* const* d_in, const int* in_sizes, int n_in,
                              void* d_out, int out_size)
{
    const float2* x     = (const float2*)d_in[0];  // (N, C, 2) f32
    const int2*   edges = (const int2*)  d_in[1];  // (E, 2) i32
    const float2* ln    = (const float2*)d_in[2];  // (E, 2) f32
    const float2* wxp   = (const float2*)d_in[3];  // (E, 2) f32

    int E = in_sizes[1] / 2;
    int n_nc = out_size / DS;                      // N*C

    int n4 = n_nc * (DSP / 2);                     // float4 count to zero
    zero_kernel<<<(n4 + 255) / 256, 256>>>(n4);

    int total = E * CCH;
    scatter_kernel<<<(total + 255) / 256, 256>>>(x, edges, ln, wxp, total);

    finalize_kernel<<<(n_nc + 255) / 256, 256>>>((float*)d_out, n_nc);
}